// round 1
// baseline (speedup 1.0000x reference)
#include <cuda_runtime.h>
#include <math.h>
#include <stdint.h>

// Problem constants
constexpr int Bd = 2;
constexpr int Td = 2048;
constexpr int Cd = 1024;
constexpr int Hd = 16;
constexpr int Dd = 64;          // head dim
constexpr int Rows = Bd * Td;   // 4096
constexpr int QKVs = 3 * Cd;    // 3072 row stride of qkv

// ---------------- scratch (device globals; no allocation allowed) ----------
__device__ float g_h   [Rows * Cd];          // LN output (reused for LN2)
__device__ float g_qkv [Rows * QKVs];        // qkv
__device__ float g_P   [(size_t)Bd * Hd * Td * Td]; // attention probs (512MB)
__device__ float g_attn[Rows * Cd];          // attention output (B,T,C layout)
__device__ float g_x1  [Rows * Cd];          // residual after attention
__device__ float g_fc  [Rows * 4 * Cd];      // MLP hidden

// ---------------- block reductions ----------------------------------------
__device__ __forceinline__ float block_reduce_sum(float v) {
    __shared__ float sm[32];
    int lane = threadIdx.x & 31, wid = threadIdx.x >> 5;
    #pragma unroll
    for (int o = 16; o; o >>= 1) v += __shfl_down_sync(0xffffffffu, v, o);
    if (lane == 0) sm[wid] = v;
    __syncthreads();
    float r;
    if (wid == 0) {
        float t = (lane < 8) ? sm[lane] : 0.0f;   // 256 threads = 8 warps
        #pragma unroll
        for (int o = 4; o; o >>= 1) t += __shfl_down_sync(0xffu, t, o);
        if (lane == 0) sm[0] = t;
    }
    __syncthreads();
    r = sm[0];
    __syncthreads();
    return r;
}

__device__ __forceinline__ float block_reduce_max(float v) {
    __shared__ float sm[32];
    int lane = threadIdx.x & 31, wid = threadIdx.x >> 5;
    #pragma unroll
    for (int o = 16; o; o >>= 1) v = fmaxf(v, __shfl_down_sync(0xffffffffu, v, o));
    if (lane == 0) sm[wid] = v;
    __syncthreads();
    float r;
    if (wid == 0) {
        float t = (lane < 8) ? sm[lane] : -INFINITY;
        #pragma unroll
        for (int o = 4; o; o >>= 1) t = fmaxf(t, __shfl_down_sync(0xffu, t, o));
        if (lane == 0) sm[0] = t;
    }
    __syncthreads();
    r = sm[0];
    __syncthreads();
    return r;
}

// ---------------- LayerNorm: one block per row (1024 cols, 256 thr) -------
__global__ __launch_bounds__(256) void ln_k(const float* __restrict__ x,
                                            const float* __restrict__ w,
                                            const float* __restrict__ b,
                                            float* __restrict__ y) {
    const int row = blockIdx.x;
    const float* xr = x + (size_t)row * Cd;
    float4 v = *(const float4*)(xr + threadIdx.x * 4);
    float s  = v.x + v.y + v.z + v.w;
    float sq = v.x * v.x + v.y * v.y + v.z * v.z + v.w * v.w;
    float sum  = block_reduce_sum(s);
    float sumq = block_reduce_sum(sq);
    float mean = sum * (1.0f / Cd);
    float var  = sumq * (1.0f / Cd) - mean * mean;
    float rstd = rsqrtf(var + 1e-5f);
    int c = threadIdx.x * 4;
    float4 wv = *(const float4*)(w + c);
    float4 bv = *(const float4*)(b + c);
    float4 o;
    o.x = (v.x - mean) * rstd * wv.x + bv.x;
    o.y = (v.y - mean) * rstd * wv.y + bv.y;
    o.z = (v.z - mean) * rstd * wv.z + bv.z;
    o.w = (v.w - mean) * rstd * wv.w + bv.w;
    *(float4*)(y + (size_t)row * Cd + c) = o;
}

// ---------------- generic tiled SGEMM with fused epilogue ------------------
// C[M,N] = A[M,K] @ B[K,N] + bias  (+res / gelu per EPI)
// EPI: 0 = bias, 1 = bias + residual, 2 = gelu(bias + .)
template <int EPI>
__global__ __launch_bounds__(256) void sgemm_k(int M, int N, int K,
                                               const float* __restrict__ A,
                                               const float* __restrict__ B,
                                               const float* __restrict__ bias,
                                               const float* __restrict__ res,
                                               float* __restrict__ C) {
    constexpr int BM = 128, BN = 128, BK = 8, TM = 8, TN = 8;
    __shared__ float As[BK][BM];
    __shared__ float Bs[BK][BN];
    const int cRow = blockIdx.y, cCol = blockIdx.x;
    const int tid = threadIdx.x;
    const int tRow = tid / 16, tCol = tid % 16;
    A += (size_t)cRow * BM * K;
    B += cCol * BN;
    C += (size_t)cRow * BM * N + cCol * BN;
    if (res) res += (size_t)cRow * BM * N + cCol * BN;
    const int aRow = tid >> 1, aCol = (tid & 1) * 4;
    const int bRow = tid >> 5, bCol = (tid & 31) * 4;
    float acc[TM][TN] = {};
    float rM[TM], rN[TN];
    for (int k0 = 0; k0 < K; k0 += BK) {
        float4 a = *(const float4*)(A + (size_t)aRow * K + k0 + aCol);
        As[aCol + 0][aRow] = a.x; As[aCol + 1][aRow] = a.y;
        As[aCol + 2][aRow] = a.z; As[aCol + 3][aRow] = a.w;
        *(float4*)(&Bs[bRow][bCol]) = *(const float4*)(B + (size_t)(k0 + bRow) * N + bCol);
        __syncthreads();
        #pragma unroll
        for (int k = 0; k < BK; k++) {
            #pragma unroll
            for (int i = 0; i < TM; i++) rM[i] = As[k][tRow * TM + i];
            #pragma unroll
            for (int j = 0; j < TN; j++) rN[j] = Bs[k][tCol * TN + j];
            #pragma unroll
            for (int i = 0; i < TM; i++)
                #pragma unroll
                for (int j = 0; j < TN; j++)
                    acc[i][j] = fmaf(rM[i], rN[j], acc[i][j]);
        }
        __syncthreads();
    }
    #pragma unroll
    for (int i = 0; i < TM; i++) {
        int row = tRow * TM + i;
        #pragma unroll
        for (int j = 0; j < TN; j++) {
            int col = tCol * TN + j;
            float c = acc[i][j] + bias[cCol * BN + col];
            if (EPI == 1) c += res[(size_t)row * N + col];
            if (EPI == 2) c = 0.5f * c * (1.0f + erff(c * 0.70710678118654752f));
            C[(size_t)row * N + col] = c;
        }
    }
}

// ---------------- attention scores: S = Q K^T * scale (lower blocks only) --
__global__ __launch_bounds__(256) void scores_k(const float* __restrict__ qkv,
                                                float* __restrict__ P) {
    const int bh = blockIdx.z;
    const int b = bh >> 4, h = bh & 15;
    const int t0 = blockIdx.y * 64, s0 = blockIdx.x * 64;
    if (s0 > t0) return;  // fully masked -> never read (stays zero from .bss)
    __shared__ float Qs[64][65];
    __shared__ float Ks[64][65];
    const int tid = threadIdx.x;
    const float* qbase = qkv + (size_t)(b * Td + t0) * QKVs + h * Dd;
    const float* kbase = qkv + (size_t)(b * Td + s0) * QKVs + Cd + h * Dd;
    #pragma unroll
    for (int i = 0; i < 4; i++) {
        int idx = tid + i * 256;
        int r = idx >> 4, c = (idx & 15) * 4;
        float4 q = *(const float4*)(qbase + (size_t)r * QKVs + c);
        Qs[r][c] = q.x; Qs[r][c + 1] = q.y; Qs[r][c + 2] = q.z; Qs[r][c + 3] = q.w;
        float4 kk = *(const float4*)(kbase + (size_t)r * QKVs + c);
        Ks[r][c] = kk.x; Ks[r][c + 1] = kk.y; Ks[r][c + 2] = kk.z; Ks[r][c + 3] = kk.w;
    }
    __syncthreads();
    const int tR = (tid / 16) * 4, tC = (tid % 16) * 4;
    float acc[4][4] = {};
    #pragma unroll
    for (int k = 0; k < 64; k++) {
        float q[4], kk[4];
        #pragma unroll
        for (int i = 0; i < 4; i++) q[i] = Qs[tR + i][k];
        #pragma unroll
        for (int j = 0; j < 4; j++) kk[j] = Ks[tC + j][k];
        #pragma unroll
        for (int i = 0; i < 4; i++)
            #pragma unroll
            for (int j = 0; j < 4; j++)
                acc[i][j] = fmaf(q[i], kk[j], acc[i][j]);
    }
    const float scale = 0.125f;  // 1/sqrt(64)
    #pragma unroll
    for (int i = 0; i < 4; i++) {
        float* rowp = P + ((size_t)bh * Td + t0 + tR + i) * Td + s0 + tC;
        #pragma unroll
        for (int j = 0; j < 4; j++) rowp[j] = acc[i][j] * scale;
    }
}

// ---------------- causal softmax per row; zero-fill to 64-block boundary ---
__global__ __launch_bounds__(256) void softmax_k(float* __restrict__ P) {
    const size_t r = blockIdx.x;               // global row over B*H*T
    const int t = (int)(r & (Td - 1));
    float* row = P + r * Td;
    const int n = t + 1;
    float m = -INFINITY;
    for (int i = threadIdx.x; i < n; i += 256) m = fmaxf(m, row[i]);
    m = block_reduce_max(m);
    float s = 0.0f;
    for (int i = threadIdx.x; i < n; i += 256) s += __expf(row[i] - m);
    s = block_reduce_sum(s);
    const float inv = 1.0f / s;
    for (int i = threadIdx.x; i < n; i += 256) row[i] = __expf(row[i] - m) * inv;
    const int fillEnd = ((t >> 6) << 6) + 64;  // zero rest of diagonal 64-block
    for (int i = n + (int)threadIdx.x; i < fillEnd; i += 256) row[i] = 0.0f;
}

// ---------------- attn_mean = 0.5*(P[0] + P[1]) ----------------------------
__global__ __launch_bounds__(256) void attnmean_k(const float* __restrict__ P,
                                                  float* __restrict__ out) {
    const size_t i = ((size_t)blockIdx.x * 256 + threadIdx.x) * 4;
    const size_t off = (size_t)Hd * Td * Td;
    float4 a = *(const float4*)(P + i);
    float4 b = *(const float4*)(P + i + off);
    float4 o;
    o.x = 0.5f * (a.x + b.x); o.y = 0.5f * (a.y + b.y);
    o.z = 0.5f * (a.z + b.z); o.w = 0.5f * (a.w + b.w);
    *(float4*)(out + i) = o;
}

// ---------------- attn_out = P @ V (triangular k-loop) ---------------------
__global__ __launch_bounds__(256) void pv_k(const float* __restrict__ P,
                                            const float* __restrict__ qkv,
                                            float* __restrict__ out) {
    const int bh = blockIdx.y;
    const int b = bh >> 4, h = bh & 15;
    const int t0 = blockIdx.x * 64;
    __shared__ float Ps[64][65];
    __shared__ float Vs[64][64];
    const int tid = threadIdx.x;
    const int tR = (tid / 16) * 4, tC = (tid % 16) * 4;
    float acc[4][4] = {};
    for (int s0 = 0; s0 <= t0; s0 += 64) {
        #pragma unroll
        for (int i = 0; i < 4; i++) {
            int idx = tid + i * 256;
            int r = idx >> 4, c = (idx & 15) * 4;
            float4 p = *(const float4*)(P + ((size_t)bh * Td + t0 + r) * Td + s0 + c);
            Ps[r][c] = p.x; Ps[r][c + 1] = p.y; Ps[r][c + 2] = p.z; Ps[r][c + 3] = p.w;
            float4 v = *(const float4*)(qkv + (size_t)(b * Td + s0 + r) * QKVs + 2 * Cd + h * Dd + c);
            *(float4*)(&Vs[r][c]) = v;
        }
        __syncthreads();
        #pragma unroll
        for (int k = 0; k < 64; k++) {
            float p[4];
            #pragma unroll
            for (int i = 0; i < 4; i++) p[i] = Ps[tR + i][k];
            float4 vv = *(const float4*)(&Vs[k][tC]);
            float v[4] = {vv.x, vv.y, vv.z, vv.w};
            #pragma unroll
            for (int i = 0; i < 4; i++)
                #pragma unroll
                for (int j = 0; j < 4; j++)
                    acc[i][j] = fmaf(p[i], v[j], acc[i][j]);
        }
        __syncthreads();
    }
    #pragma unroll
    for (int i = 0; i < 4; i++) {
        float* op = out + (size_t)(b * Td + t0 + tR + i) * Cd + h * Dd + tC;
        #pragma unroll
        for (int j = 0; j < 4; j++) op[j] = acc[i][j];
    }
}

// ---------------- launch ---------------------------------------------------
extern "C" void kernel_launch(void* const* d_in, const int* in_sizes, int n_in,
                              void* d_out, int out_size) {
    const float* x      = (const float*)d_in[0];
    const float* ln1_w  = (const float*)d_in[1];
    const float* ln1_b  = (const float*)d_in[2];
    const float* w_qkv  = (const float*)d_in[3];
    const float* b_qkv  = (const float*)d_in[4];
    const float* w_proj = (const float*)d_in[5];
    const float* b_proj = (const float*)d_in[6];
    const float* ln2_w  = (const float*)d_in[7];
    const float* ln2_b  = (const float*)d_in[8];
    const float* w_fc   = (const float*)d_in[9];
    const float* b_fc   = (const float*)d_in[10];
    const float* w_fc2  = (const float*)d_in[11];
    const float* b_fc2  = (const float*)d_in[12];

    float* out_x    = (float*)d_out;                        // [B,T,C]
    float* out_attn = (float*)d_out + (size_t)Rows * Cd;    // [H,T,T]

    float *gh, *gqkv, *gP, *gattn, *gx1, *gfc;
    cudaGetSymbolAddress((void**)&gh,   g_h);
    cudaGetSymbolAddress((void**)&gqkv, g_qkv);
    cudaGetSymbolAddress((void**)&gP,   g_P);
    cudaGetSymbolAddress((void**)&gattn,g_attn);
    cudaGetSymbolAddress((void**)&gx1,  g_x1);
    cudaGetSymbolAddress((void**)&gfc,  g_fc);

    // 1. LN1
    ln_k<<<Rows, 256>>>(x, ln1_w, ln1_b, gh);
    // 2. QKV = LN1 @ w_qkv + b_qkv          [4096,1024]@[1024,3072]
    sgemm_k<0><<<dim3(QKVs / 128, Rows / 128), 256>>>(Rows, QKVs, Cd, gh, w_qkv, b_qkv, nullptr, gqkv);
    // 3. scores (lower-triangular blocks)
    scores_k<<<dim3(Td / 64, Td / 64, Bd * Hd), 256>>>(gqkv, gP);
    // 4. softmax + diagonal-block zero-fill
    softmax_k<<<Bd * Hd * Td, 256>>>(gP);
    // 5. attn mean over batch -> output
    attnmean_k<<<(unsigned)((size_t)Hd * Td * Td / 4 / 256), 256>>>(gP, out_attn);
    // 6. attn_out = P @ V
    pv_k<<<dim3(Td / 64, Bd * Hd), 256>>>(gP, gqkv, gattn);
    // 7. x1 = attn_out @ w_proj + b_proj + x
    sgemm_k<1><<<dim3(Cd / 128, Rows / 128), 256>>>(Rows, Cd, Cd, gattn, w_proj, b_proj, x, gx1);
    // 8. LN2
    ln_k<<<Rows, 256>>>(gx1, ln2_w, ln2_b, gh);
    // 9. fc = gelu(LN2 @ w_fc + b_fc)       [4096,1024]@[1024,4096]
    sgemm_k<2><<<dim3(4 * Cd / 128, Rows / 128), 256>>>(Rows, 4 * Cd, Cd, gh, w_fc, b_fc, nullptr, gfc);
    // 10. out = fc @ w_fc2 + b_fc2 + x1     [4096,4096]@[4096,1024]
    sgemm_k<1><<<dim3(Cd / 128, Rows / 128), 256>>>(Rows, Cd, 4 * Cd, gfc, w_fc2, b_fc2, gx1, out_x);
}

// round 3
// speedup vs baseline: 1.1074x; 1.1074x over previous
#include <cuda_runtime.h>
#include <math.h>
#include <stdint.h>

// Problem constants
constexpr int Bd = 2;
constexpr int Td = 2048;
constexpr int Cd = 1024;
constexpr int Hd = 16;
constexpr int Rows = Bd * Td;   // 4096
constexpr int QKVs = 3 * Cd;    // 3072

// ---------------- scratch (device globals) ---------------------------------
__device__ float g_h   [Rows * Cd];
__device__ float g_qkv [Rows * QKVs];
__device__ float g_P   [(size_t)Bd * Hd * Td * Td];
__device__ float g_attn[Rows * Cd];
__device__ float g_x1  [Rows * Cd];
__device__ float g_fc  [Rows * 4 * Cd];

// ---------------- mma.sync tf32 m16n8k8 + 3xTF32 helpers -------------------
__device__ __forceinline__ void mma_tf32(float* c, const uint32_t* a, const uint32_t* b) {
    asm volatile(
        "mma.sync.aligned.m16n8k8.row.col.f32.tf32.tf32.f32 "
        "{%0,%1,%2,%3}, {%4,%5,%6,%7}, {%8,%9}, {%0,%1,%2,%3};\n"
        : "+f"(c[0]), "+f"(c[1]), "+f"(c[2]), "+f"(c[3])
        : "r"(a[0]), "r"(a[1]), "r"(a[2]), "r"(a[3]), "r"(b[0]), "r"(b[1]));
}

__device__ __forceinline__ uint32_t f2tf32(float x) {
    uint32_t r;
    asm("cvt.rna.tf32.f32 %0, %1;\n" : "=r"(r) : "f"(x));
    return r;
}
// decompose: hi = tf32(x), lo = tf32(x - hi)
__device__ __forceinline__ void split_tf32(float x, uint32_t& hi, uint32_t& lo) {
    hi = f2tf32(x);
    lo = f2tf32(x - __uint_as_float(hi));
}

// ---------------- block reductions -----------------------------------------
__device__ __forceinline__ float block_reduce_sum(float v) {
    __shared__ float sm[32];
    int lane = threadIdx.x & 31, wid = threadIdx.x >> 5;
    #pragma unroll
    for (int o = 16; o; o >>= 1) v += __shfl_down_sync(0xffffffffu, v, o);
    if (lane == 0) sm[wid] = v;
    __syncthreads();
    float r;
    if (wid == 0) {
        float t = (lane < 8) ? sm[lane] : 0.0f;
        #pragma unroll
        for (int o = 4; o; o >>= 1) t += __shfl_down_sync(0xffu, t, o);
        if (lane == 0) sm[0] = t;
    }
    __syncthreads();
    r = sm[0];
    __syncthreads();
    return r;
}

__device__ __forceinline__ float block_reduce_max(float v) {
    __shared__ float sm[32];
    int lane = threadIdx.x & 31, wid = threadIdx.x >> 5;
    #pragma unroll
    for (int o = 16; o; o >>= 1) v = fmaxf(v, __shfl_down_sync(0xffffffffu, v, o));
    if (lane == 0) sm[wid] = v;
    __syncthreads();
    float r;
    if (wid == 0) {
        float t = (lane < 8) ? sm[lane] : -INFINITY;
        #pragma unroll
        for (int o = 4; o; o >>= 1) t = fmaxf(t, __shfl_down_sync(0xffu, t, o));
        if (lane == 0) sm[0] = t;
    }
    __syncthreads();
    r = sm[0];
    __syncthreads();
    return r;
}

// ---------------- LayerNorm ------------------------------------------------
__global__ __launch_bounds__(256) void ln_k(const float* __restrict__ x,
                                            const float* __restrict__ w,
                                            const float* __restrict__ b,
                                            float* __restrict__ y) {
    const int row = blockIdx.x;
    const float* xr = x + (size_t)row * Cd;
    float4 v = *(const float4*)(xr + threadIdx.x * 4);
    float s  = v.x + v.y + v.z + v.w;
    float sq = v.x * v.x + v.y * v.y + v.z * v.z + v.w * v.w;
    float sum  = block_reduce_sum(s);
    float sumq = block_reduce_sum(sq);
    float mean = sum * (1.0f / Cd);
    float var  = sumq * (1.0f / Cd) - mean * mean;
    float rstd = rsqrtf(var + 1e-5f);
    int c = threadIdx.x * 4;
    float4 wv = *(const float4*)(w + c);
    float4 bv = *(const float4*)(b + c);
    float4 o;
    o.x = (v.x - mean) * rstd * wv.x + bv.x;
    o.y = (v.y - mean) * rstd * wv.y + bv.y;
    o.z = (v.z - mean) * rstd * wv.z + bv.z;
    o.w = (v.w - mean) * rstd * wv.w + bv.w;
    *(float4*)(y + (size_t)row * Cd + c) = o;
}

// ---------------- 3xTF32 tensor-core GEMM with fused epilogue --------------
// C[M,N] = A[M,K] @ B[K,N] + bias; EPI: 0 bias, 1 bias+res, 2 gelu(bias+.)
template <int EPI>
__global__ __launch_bounds__(256) void tgemm_k(int M, int N, int K,
                                               const float* __restrict__ A,
                                               const float* __restrict__ B,
                                               const float* __restrict__ bias,
                                               const float* __restrict__ res,
                                               float* __restrict__ C) {
    constexpr int BM = 128, BN = 128, BK = 16;
    __shared__ float As[BM][BK + 4];   // stride 20: conflict-free frag loads
    __shared__ float Bs[BK][BN + 8];   // stride 136: conflict-free frag loads
    const int tid = threadIdx.x, lane = tid & 31, warp = tid >> 5;
    const int warpM = warp >> 2, warpN = warp & 3;       // 2 x 4 warps
    const size_t bM = (size_t)blockIdx.y * BM, bN = (size_t)blockIdx.x * BN;

    float acc[4][4][4] = {};
    for (int k0 = 0; k0 < K; k0 += BK) {
        #pragma unroll
        for (int i = 0; i < 2; i++) {
            int idx = tid + i * 256;
            int r = idx >> 2, c = (idx & 3) * 4;
            *(float4*)&As[r][c] = *(const float4*)(A + (bM + r) * K + k0 + c);
            int rb = idx >> 5, cb = (idx & 31) * 4;
            *(float4*)&Bs[rb][cb] = *(const float4*)(B + (size_t)(k0 + rb) * N + bN + cb);
        }
        __syncthreads();
        #pragma unroll
        for (int ks = 0; ks < BK; ks += 8) {
            uint32_t ah[4][4], al[4][4], bh[4][2], bl[4][2];
            #pragma unroll
            for (int mt = 0; mt < 4; mt++) {
                int r = warpM * 64 + mt * 16 + (lane >> 2);
                int cc = ks + (lane & 3);
                split_tf32(As[r][cc],      ah[mt][0], al[mt][0]);
                split_tf32(As[r + 8][cc],  ah[mt][1], al[mt][1]);
                split_tf32(As[r][cc + 4],  ah[mt][2], al[mt][2]);
                split_tf32(As[r + 8][cc + 4], ah[mt][3], al[mt][3]);
            }
            #pragma unroll
            for (int nt = 0; nt < 4; nt++) {
                int n = warpN * 32 + nt * 8 + (lane >> 2);
                split_tf32(Bs[ks + (lane & 3)][n],     bh[nt][0], bl[nt][0]);
                split_tf32(Bs[ks + (lane & 3) + 4][n], bh[nt][1], bl[nt][1]);
            }
            #pragma unroll
            for (int mt = 0; mt < 4; mt++)
                #pragma unroll
                for (int nt = 0; nt < 4; nt++) {
                    mma_tf32(acc[mt][nt], al[mt], bh[nt]);
                    mma_tf32(acc[mt][nt], ah[mt], bl[nt]);
                    mma_tf32(acc[mt][nt], ah[mt], bh[nt]);
                }
        }
        __syncthreads();
    }
    // epilogue
    #pragma unroll
    for (int mt = 0; mt < 4; mt++) {
        #pragma unroll
        for (int nt = 0; nt < 4; nt++) {
            size_t r0 = bM + warpM * 64 + mt * 16 + (lane >> 2);
            size_t cb = bN + warpN * 32 + nt * 8 + (lane & 3) * 2;
            float b0 = bias[cb], b1 = bias[cb + 1];
            #pragma unroll
            for (int half = 0; half < 2; half++) {
                size_t r = r0 + half * 8;
                float v0 = acc[mt][nt][half * 2 + 0] + b0;
                float v1 = acc[mt][nt][half * 2 + 1] + b1;
                if (EPI == 1) {
                    const float* rp = res + r * N + cb;
                    v0 += rp[0]; v1 += rp[1];
                }
                if (EPI == 2) {
                    v0 = 0.5f * v0 * (1.0f + erff(v0 * 0.70710678118654752f));
                    v1 = 0.5f * v1 * (1.0f + erff(v1 * 0.70710678118654752f));
                }
                float2 o = make_float2(v0, v1);
                *(float2*)(C + r * N + cb) = o;
            }
        }
    }
}

// ---------------- scores: S = Q K^T * scale (lower blocks), 3xTF32 ---------
__global__ __launch_bounds__(128) void scores_tc(const float* __restrict__ qkv,
                                                 float* __restrict__ P) {
    const int bh = blockIdx.z;
    const int b = bh >> 4, h = bh & 15;
    const int t0 = blockIdx.y * 64, s0 = blockIdx.x * 64;
    if (s0 > t0) return;
    __shared__ float Qs[64][76];   // row-major [m][k], stride 76 conflict-free
    __shared__ float Ks[64][76];   // row-major [n][k]
    const int tid = threadIdx.x, lane = tid & 31, warp = tid >> 5;
    const float* qb = qkv + (size_t)(b * Td + t0) * QKVs + h * 64;
    const float* kb = qkv + (size_t)(b * Td + s0) * QKVs + Cd + h * 64;
    #pragma unroll
    for (int i = 0; i < 8; i++) {
        int idx = tid + i * 128;
        int r = idx >> 4, c = (idx & 15) * 4;
        *(float4*)&Qs[r][c] = *(const float4*)(qb + (size_t)r * QKVs + c);
        *(float4*)&Ks[r][c] = *(const float4*)(kb + (size_t)r * QKVs + c);
    }
    __syncthreads();
    const int warpM = warp >> 1, warpN = warp & 1;  // 2 x 2 warps, 32x32 each
    float acc[2][4][4] = {};
    #pragma unroll
    for (int ks = 0; ks < 64; ks += 8) {
        uint32_t ah[2][4], al[2][4], bh[4][2], bl[4][2];
        #pragma unroll
        for (int mt = 0; mt < 2; mt++) {
            int r = warpM * 32 + mt * 16 + (lane >> 2);
            int c = ks + (lane & 3);
            split_tf32(Qs[r][c],          ah[mt][0], al[mt][0]);
            split_tf32(Qs[r + 8][c],      ah[mt][1], al[mt][1]);
            split_tf32(Qs[r][c + 4],      ah[mt][2], al[mt][2]);
            split_tf32(Qs[r + 8][c + 4],  ah[mt][3], al[mt][3]);
        }
        #pragma unroll
        for (int nt = 0; nt < 4; nt++) {
            int n = warpN * 32 + nt * 8 + (lane >> 2);
            int c = ks + (lane & 3);
            split_tf32(Ks[n][c],     bh[nt][0], bl[nt][0]);
            split_tf32(Ks[n][c + 4], bh[nt][1], bl[nt][1]);
        }
        #pragma unroll
        for (int mt = 0; mt < 2; mt++)
            #pragma unroll
            for (int nt = 0; nt < 4; nt++) {
                mma_tf32(acc[mt][nt], al[mt], bh[nt]);
                mma_tf32(acc[mt][nt], ah[mt], bl[nt]);
                mma_tf32(acc[mt][nt], ah[mt], bh[nt]);
            }
    }
    const float scale = 0.125f;
    #pragma unroll
    for (int mt = 0; mt < 2; mt++) {
        #pragma unroll
        for (int nt = 0; nt < 4; nt++) {
            int r0 = t0 + warpM * 32 + mt * 16 + (lane >> 2);
            int cb = s0 + warpN * 32 + nt * 8 + (lane & 3) * 2;
            #pragma unroll
            for (int half = 0; half < 2; half++) {
                int r = r0 + half * 8;
                float2 o = make_float2(acc[mt][nt][half * 2] * scale,
                                       acc[mt][nt][half * 2 + 1] * scale);
                *(float2*)(P + ((size_t)bh * Td + r) * Td + cb) = o;
            }
        }
    }
}

// ---------------- causal softmax per row (3-pass, L2-resident) -------------
__global__ __launch_bounds__(256) void softmax_k(float* __restrict__ P) {
    const size_t r = blockIdx.x;
    const int t = (int)(r & (Td - 1));
    float* row = P + r * Td;
    const int n = t + 1;
    float m = -INFINITY;
    for (int i = threadIdx.x; i < n; i += 256) m = fmaxf(m, row[i]);
    m = block_reduce_max(m);
    float s = 0.0f;
    for (int i = threadIdx.x; i < n; i += 256) s += __expf(row[i] - m);
    s = block_reduce_sum(s);
    const float inv = 1.0f / s;
    for (int i = threadIdx.x; i < n; i += 256) row[i] = __expf(row[i] - m) * inv;
    const int fillEnd = ((t >> 6) << 6) + 64;
    for (int i = n + (int)threadIdx.x; i < fillEnd; i += 256) row[i] = 0.0f;
}

// ---------------- attn_mean: lower reads only, zeros written directly ------
__global__ __launch_bounds__(256) void attnmean_k(const float* __restrict__ P,
                                                  float* __restrict__ out) {
    const size_t i4 = (size_t)blockIdx.x * 256 + threadIdx.x;
    const int scol = (int)(i4 & (Td / 4 - 1)) * 4;
    const int t = (int)((i4 >> 9) & (Td - 1));
    const size_t off = (size_t)Hd * Td * Td;
    float4 o;
    if (scol > t) {
        o = make_float4(0.f, 0.f, 0.f, 0.f);
    } else {
        float4 a = *(const float4*)(P + i4 * 4);
        float4 b = *(const float4*)(P + i4 * 4 + off);
        o.x = 0.5f * (a.x + b.x); o.y = 0.5f * (a.y + b.y);
        o.z = 0.5f * (a.z + b.z); o.w = 0.5f * (a.w + b.w);
    }
    *(float4*)(out + i4 * 4) = o;
}

// ---------------- attn_out = P @ V (triangular), 3xTF32 --------------------
__global__ __launch_bounds__(128) void pv_tc(const float* __restrict__ P,
                                             const float* __restrict__ qkv,
                                             float* __restrict__ out) {
    const int bh = blockIdx.y;
    const int b = bh >> 4, h = bh & 15;
    const int t0 = blockIdx.x * 64;
    __shared__ float Ps[64][76];   // [m][k] stride 76
    __shared__ float Vs[64][72];   // [k][n] stride 72 conflict-free b-frags
    const int tid = threadIdx.x, lane = tid & 31, warp = tid >> 5;
    const int warpM = warp >> 1, warpN = warp & 1;
    float acc[2][4][4] = {};
    for (int s0 = 0; s0 <= t0; s0 += 64) {
        #pragma unroll
        for (int i = 0; i < 8; i++) {
            int idx = tid + i * 128;
            int r = idx >> 4, c = (idx & 15) * 4;
            *(float4*)&Ps[r][c] = *(const float4*)(P + ((size_t)bh * Td + t0 + r) * Td + s0 + c);
            *(float4*)&Vs[r][c] = *(const float4*)(qkv + (size_t)(b * Td + s0 + r) * QKVs + 2 * Cd + h * 64 + c);
        }
        __syncthreads();
        #pragma unroll
        for (int ks = 0; ks < 64; ks += 8) {
            uint32_t ah[2][4], al[2][4], bh[4][2], bl[4][2];
            #pragma unroll
            for (int mt = 0; mt < 2; mt++) {
                int r = warpM * 32 + mt * 16 + (lane >> 2);
                int c = ks + (lane & 3);
                split_tf32(Ps[r][c],         ah[mt][0], al[mt][0]);
                split_tf32(Ps[r + 8][c],     ah[mt][1], al[mt][1]);
                split_tf32(Ps[r][c + 4],     ah[mt][2], al[mt][2]);
                split_tf32(Ps[r + 8][c + 4], ah[mt][3], al[mt][3]);
            }
            #pragma unroll
            for (int nt = 0; nt < 4; nt++) {
                int n = warpN * 32 + nt * 8 + (lane >> 2);
                split_tf32(Vs[ks + (lane & 3)][n],     bh[nt][0], bl[nt][0]);
                split_tf32(Vs[ks + (lane & 3) + 4][n], bh[nt][1], bl[nt][1]);
            }
            #pragma unroll
            for (int mt = 0; mt < 2; mt++)
                #pragma unroll
                for (int nt = 0; nt < 4; nt++) {
                    mma_tf32(acc[mt][nt], al[mt], bh[nt]);
                    mma_tf32(acc[mt][nt], ah[mt], bl[nt]);
                    mma_tf32(acc[mt][nt], ah[mt], bh[nt]);
                }
        }
        __syncthreads();
    }
    #pragma unroll
    for (int mt = 0; mt < 2; mt++) {
        #pragma unroll
        for (int nt = 0; nt < 4; nt++) {
            int r0 = t0 + warpM * 32 + mt * 16 + (lane >> 2);
            int cb = warpN * 32 + nt * 8 + (lane & 3) * 2;
            #pragma unroll
            for (int half = 0; half < 2; half++) {
                int r = r0 + half * 8;
                float2 o = make_float2(acc[mt][nt][half * 2], acc[mt][nt][half * 2 + 1]);
                *(float2*)(out + (size_t)(b * Td + r) * Cd + h * 64 + cb) = o;
            }
        }
    }
}

// ---------------- launch ---------------------------------------------------
extern "C" void kernel_launch(void* const* d_in, const int* in_sizes, int n_in,
                              void* d_out, int out_size) {
    const float* x      = (const float*)d_in[0];
    const float* ln1_w  = (const float*)d_in[1];
    const float* ln1_b  = (const float*)d_in[2];
    const float* w_qkv  = (const float*)d_in[3];
    const float* b_qkv  = (const float*)d_in[4];
    const float* w_proj = (const float*)d_in[5];
    const float* b_proj = (const float*)d_in[6];
    const float* ln2_w  = (const float*)d_in[7];
    const float* ln2_b  = (const float*)d_in[8];
    const float* w_fc   = (const float*)d_in[9];
    const float* b_fc   = (const float*)d_in[10];
    const float* w_fc2  = (const float*)d_in[11];
    const float* b_fc2  = (const float*)d_in[12];

    float* out_x    = (float*)d_out;
    float* out_attn = (float*)d_out + (size_t)Rows * Cd;

    float *gh, *gqkv, *gP, *gattn, *gx1, *gfc;
    cudaGetSymbolAddress((void**)&gh,   g_h);
    cudaGetSymbolAddress((void**)&gqkv, g_qkv);
    cudaGetSymbolAddress((void**)&gP,   g_P);
    cudaGetSymbolAddress((void**)&gattn,g_attn);
    cudaGetSymbolAddress((void**)&gx1,  g_x1);
    cudaGetSymbolAddress((void**)&gfc,  g_fc);

    ln_k<<<Rows, 256>>>(x, ln1_w, ln1_b, gh);
    tgemm_k<0><<<dim3(QKVs / 128, Rows / 128), 256>>>(Rows, QKVs, Cd, gh, w_qkv, b_qkv, nullptr, gqkv);
    scores_tc<<<dim3(Td / 64, Td / 64, Bd * Hd), 128>>>(gqkv, gP);
    softmax_k<<<Bd * Hd * Td, 256>>>(gP);
    attnmean_k<<<(unsigned)((size_t)Hd * Td * Td / 4 / 256), 256>>>(gP, out_attn);
    pv_tc<<<dim3(Td / 64, Bd * Hd), 128>>>(gP, gqkv, gattn);
    tgemm_k<1><<<dim3(Cd / 128, Rows / 128), 256>>>(Rows, Cd, Cd, gattn, w_proj, b_proj, x, gx1);
    ln_k<<<Rows, 256>>>(gx1, ln2_w, ln2_b, gh);
    tgemm_k<2><<<dim3(4 * Cd / 128, Rows / 128), 256>>>(Rows, 4 * Cd, Cd, gh, w_fc, b_fc, nullptr, gfc);
    tgemm_k<1><<<dim3(Cd / 128, Rows / 128), 256>>>(Rows, Cd, 4 * Cd, gfc, w_fc2, b_fc2, gx1, out_x);
}

// round 5
// speedup vs baseline: 1.3537x; 1.2224x over previous
#include <cuda_runtime.h>
#include <math.h>
#include <stdint.h>

// Problem constants
constexpr int Bd = 2;
constexpr int Td = 2048;
constexpr int Cd = 1024;
constexpr int Hd = 16;
constexpr int Rows = Bd * Td;   // 4096
constexpr int QKVs = 3 * Cd;    // 3072

// ---------------- scratch (device globals) ---------------------------------
__device__ float g_h   [Rows * Cd];
__device__ float g_qkv [Rows * QKVs];
__device__ float g_P   [(size_t)Bd * Hd * Td * Td];
__device__ float g_attn[Rows * Cd];
__device__ float g_x1  [Rows * Cd];
__device__ float g_fc  [Rows * 4 * Cd];

// ---------------- mma.sync tf32 m16n8k8 + 3xTF32 helpers -------------------
__device__ __forceinline__ void mma_tf32(float* c, const uint32_t* a, const uint32_t* b) {
    asm volatile(
        "mma.sync.aligned.m16n8k8.row.col.f32.tf32.tf32.f32 "
        "{%0,%1,%2,%3}, {%4,%5,%6,%7}, {%8,%9}, {%0,%1,%2,%3};\n"
        : "+f"(c[0]), "+f"(c[1]), "+f"(c[2]), "+f"(c[3])
        : "r"(a[0]), "r"(a[1]), "r"(a[2]), "r"(a[3]), "r"(b[0]), "r"(b[1]));
}

__device__ __forceinline__ float f2tf32f(float x) {
    uint32_t r;
    asm("cvt.rna.tf32.f32 %0, %1;\n" : "=r"(r) : "f"(x));
    return __uint_as_float(r);
}
// hi = tf32(x); lo = tf32(x - hi)
__device__ __forceinline__ void split2(float x, float& hi, float& lo) {
    hi = f2tf32f(x);
    lo = f2tf32f(x - hi);
}
__device__ __forceinline__ void split4(float4 v, float4& hi, float4& lo) {
    split2(v.x, hi.x, lo.x); split2(v.y, hi.y, lo.y);
    split2(v.z, hi.z, lo.z); split2(v.w, hi.w, lo.w);
}

// ---------------- block reductions -----------------------------------------
__device__ __forceinline__ float block_reduce_sum(float v) {
    __shared__ float sm[32];
    int lane = threadIdx.x & 31, wid = threadIdx.x >> 5;
    #pragma unroll
    for (int o = 16; o; o >>= 1) v += __shfl_down_sync(0xffffffffu, v, o);
    if (lane == 0) sm[wid] = v;
    __syncthreads();
    float r;
    if (wid == 0) {
        float t = (lane < 8) ? sm[lane] : 0.0f;
        #pragma unroll
        for (int o = 4; o; o >>= 1) t += __shfl_down_sync(0xffu, t, o);
        if (lane == 0) sm[0] = t;
    }
    __syncthreads();
    r = sm[0];
    __syncthreads();
    return r;
}

__device__ __forceinline__ float block_reduce_max(float v) {
    __shared__ float sm[32];
    int lane = threadIdx.x & 31, wid = threadIdx.x >> 5;
    #pragma unroll
    for (int o = 16; o; o >>= 1) v = fmaxf(v, __shfl_down_sync(0xffffffffu, v, o));
    if (lane == 0) sm[wid] = v;
    __syncthreads();
    float r;
    if (wid == 0) {
        float t = (lane < 8) ? sm[lane] : -INFINITY;
        #pragma unroll
        for (int o = 4; o; o >>= 1) t = fmaxf(t, __shfl_down_sync(0xffu, t, o));
        if (lane == 0) sm[0] = t;
    }
    __syncthreads();
    r = sm[0];
    __syncthreads();
    return r;
}

// ---------------- LayerNorm ------------------------------------------------
__global__ __launch_bounds__(256) void ln_k(const float* __restrict__ x,
                                            const float* __restrict__ w,
                                            const float* __restrict__ b,
                                            float* __restrict__ y) {
    const int row = blockIdx.x;
    const float* xr = x + (size_t)row * Cd;
    float4 v = *(const float4*)(xr + threadIdx.x * 4);
    float s  = v.x + v.y + v.z + v.w;
    float sq = v.x * v.x + v.y * v.y + v.z * v.z + v.w * v.w;
    float sum  = block_reduce_sum(s);
    float sumq = block_reduce_sum(sq);
    float mean = sum * (1.0f / Cd);
    float var  = sumq * (1.0f / Cd) - mean * mean;
    float rstd = rsqrtf(var + 1e-5f);
    int c = threadIdx.x * 4;
    float4 wv = *(const float4*)(w + c);
    float4 bv = *(const float4*)(b + c);
    float4 o;
    o.x = (v.x - mean) * rstd * wv.x + bv.x;
    o.y = (v.y - mean) * rstd * wv.y + bv.y;
    o.z = (v.z - mean) * rstd * wv.z + bv.z;
    o.w = (v.w - mean) * rstd * wv.w + bv.w;
    *(float4*)(y + (size_t)row * Cd + c) = o;
}

// ---------------- 3xTF32 GEMM, precomputed hi/lo smem, reg prefetch --------
// C[M,N] = A[M,K] @ B[K,N] + bias; EPI: 0 bias, 1 bias+res, 2 gelu(bias+.)
template <int EPI>
__global__ __launch_bounds__(256) void tgemm_k(int M, int N, int K,
                                               const float* __restrict__ A,
                                               const float* __restrict__ B,
                                               const float* __restrict__ bias,
                                               const float* __restrict__ res,
                                               float* __restrict__ C) {
    constexpr int BM = 128, BN = 128, BK = 16;
    __shared__ float Ah[BM][BK + 4];   // stride 20 (conflict-free frags)
    __shared__ float Al[BM][BK + 4];
    __shared__ float Bh[BK][BN + 8];   // stride 136 (conflict-free frags)
    __shared__ float Bl[BK][BN + 8];
    const int tid = threadIdx.x, lane = tid & 31, warp = tid >> 5;
    const int warpM = warp >> 2, warpN = warp & 3;       // 2 x 4 warps
    const size_t bM = (size_t)blockIdx.y * BM, bN = (size_t)blockIdx.x * BN;

    const int aRow = tid >> 2, aCol = (tid & 3) * 4;     // + 64*i rows
    const int bRow = tid >> 5, bCol = (tid & 31) * 4;    // + 8*i rows

    float4 ra[2], rb[2];
    #pragma unroll
    for (int i = 0; i < 2; i++) {
        ra[i] = *(const float4*)(A + (bM + aRow + 64 * i) * K + aCol);
        rb[i] = *(const float4*)(B + (size_t)(bRow + 8 * i) * N + bN + bCol);
    }

    float acc[4][4][4] = {};
    for (int k0 = 0; k0 < K; k0 += BK) {
        // split current regs into hi/lo smem tiles
        #pragma unroll
        for (int i = 0; i < 2; i++) {
            float4 hi, lo;
            split4(ra[i], hi, lo);
            *(float4*)&Ah[aRow + 64 * i][aCol] = hi;
            *(float4*)&Al[aRow + 64 * i][aCol] = lo;
            split4(rb[i], hi, lo);
            *(float4*)&Bh[bRow + 8 * i][bCol] = hi;
            *(float4*)&Bl[bRow + 8 * i][bCol] = lo;
        }
        __syncthreads();
        if (k0 + BK < K) {
            #pragma unroll
            for (int i = 0; i < 2; i++) {
                ra[i] = *(const float4*)(A + (bM + aRow + 64 * i) * K + k0 + BK + aCol);
                rb[i] = *(const float4*)(B + (size_t)(k0 + BK + bRow + 8 * i) * N + bN + bCol);
            }
        }
        #pragma unroll
        for (int ks = 0; ks < BK; ks += 8) {
            uint32_t ah[4][4], al[4][4], bh[4][2], bl[4][2];
            #pragma unroll
            for (int mt = 0; mt < 4; mt++) {
                int r = warpM * 64 + mt * 16 + (lane >> 2);
                int cc = ks + (lane & 3);
                ah[mt][0] = __float_as_uint(Ah[r][cc]);
                ah[mt][1] = __float_as_uint(Ah[r + 8][cc]);
                ah[mt][2] = __float_as_uint(Ah[r][cc + 4]);
                ah[mt][3] = __float_as_uint(Ah[r + 8][cc + 4]);
                al[mt][0] = __float_as_uint(Al[r][cc]);
                al[mt][1] = __float_as_uint(Al[r + 8][cc]);
                al[mt][2] = __float_as_uint(Al[r][cc + 4]);
                al[mt][3] = __float_as_uint(Al[r + 8][cc + 4]);
            }
            #pragma unroll
            for (int nt = 0; nt < 4; nt++) {
                int n = warpN * 32 + nt * 8 + (lane >> 2);
                int kk = ks + (lane & 3);
                bh[nt][0] = __float_as_uint(Bh[kk][n]);
                bh[nt][1] = __float_as_uint(Bh[kk + 4][n]);
                bl[nt][0] = __float_as_uint(Bl[kk][n]);
                bl[nt][1] = __float_as_uint(Bl[kk + 4][n]);
            }
            #pragma unroll
            for (int mt = 0; mt < 4; mt++)
                #pragma unroll
                for (int nt = 0; nt < 4; nt++) {
                    mma_tf32(acc[mt][nt], al[mt], bh[nt]);
                    mma_tf32(acc[mt][nt], ah[mt], bl[nt]);
                    mma_tf32(acc[mt][nt], ah[mt], bh[nt]);
                }
        }
        __syncthreads();
    }
    // epilogue
    #pragma unroll
    for (int mt = 0; mt < 4; mt++) {
        #pragma unroll
        for (int nt = 0; nt < 4; nt++) {
            size_t r0 = bM + warpM * 64 + mt * 16 + (lane >> 2);
            size_t cb = bN + warpN * 32 + nt * 8 + (lane & 3) * 2;
            float b0 = bias[cb], b1 = bias[cb + 1];
            #pragma unroll
            for (int half = 0; half < 2; half++) {
                size_t r = r0 + half * 8;
                float v0 = acc[mt][nt][half * 2 + 0] + b0;
                float v1 = acc[mt][nt][half * 2 + 1] + b1;
                if (EPI == 1) {
                    const float* rp = res + r * N + cb;
                    v0 += rp[0]; v1 += rp[1];
                }
                if (EPI == 2) {
                    v0 = 0.5f * v0 * (1.0f + erff(v0 * 0.70710678118654752f));
                    v1 = 0.5f * v1 * (1.0f + erff(v1 * 0.70710678118654752f));
                }
                *(float2*)(C + r * N + cb) = make_float2(v0, v1);
            }
        }
    }
}

// ---------------- scores: S = Q K^T * scale (lower blocks), 3xTF32 ---------
__global__ __launch_bounds__(128) void scores_tc(const float* __restrict__ qkv,
                                                 float* __restrict__ P) {
    const int bh = blockIdx.z;
    const int b = bh >> 4, h = bh & 15;
    const int t0 = blockIdx.y * 64, s0 = blockIdx.x * 64;
    if (s0 > t0) return;
    __shared__ float Qh[64][36], Ql[64][36];   // [m][k], 32-wide K slab
    __shared__ float Kh[64][36], Kl[64][36];   // [n][k]
    const int tid = threadIdx.x, lane = tid & 31, warp = tid >> 5;
    const int warpM = warp >> 1, warpN = warp & 1;  // 2x2 warps, 32x32 each
    const float* qb = qkv + (size_t)(b * Td + t0) * QKVs + h * 64;
    const float* kb = qkv + (size_t)(b * Td + s0) * QKVs + Cd + h * 64;
    float acc[2][4][4] = {};
    for (int kk = 0; kk < 64; kk += 32) {
        #pragma unroll
        for (int i = 0; i < 4; i++) {
            int idx = tid + i * 128;
            int r = idx >> 3, c = (idx & 7) * 4;
            float4 hi, lo;
            split4(*(const float4*)(qb + (size_t)r * QKVs + kk + c), hi, lo);
            *(float4*)&Qh[r][c] = hi; *(float4*)&Ql[r][c] = lo;
            split4(*(const float4*)(kb + (size_t)r * QKVs + kk + c), hi, lo);
            *(float4*)&Kh[r][c] = hi; *(float4*)&Kl[r][c] = lo;
        }
        __syncthreads();
        #pragma unroll
        for (int ks = 0; ks < 32; ks += 8) {
            uint32_t ah[2][4], al[2][4], bh[4][2], bl[4][2];
            #pragma unroll
            for (int mt = 0; mt < 2; mt++) {
                int r = warpM * 32 + mt * 16 + (lane >> 2);
                int c = ks + (lane & 3);
                ah[mt][0] = __float_as_uint(Qh[r][c]);
                ah[mt][1] = __float_as_uint(Qh[r + 8][c]);
                ah[mt][2] = __float_as_uint(Qh[r][c + 4]);
                ah[mt][3] = __float_as_uint(Qh[r + 8][c + 4]);
                al[mt][0] = __float_as_uint(Ql[r][c]);
                al[mt][1] = __float_as_uint(Ql[r + 8][c]);
                al[mt][2] = __float_as_uint(Ql[r][c + 4]);
                al[mt][3] = __float_as_uint(Ql[r + 8][c + 4]);
            }
            #pragma unroll
            for (int nt = 0; nt < 4; nt++) {
                int n = warpN * 32 + nt * 8 + (lane >> 2);
                int c = ks + (lane & 3);
                bh[nt][0] = __float_as_uint(Kh[n][c]);
                bh[nt][1] = __float_as_uint(Kh[n][c + 4]);
                bl[nt][0] = __float_as_uint(Kl[n][c]);
                bl[nt][1] = __float_as_uint(Kl[n][c + 4]);
            }
            #pragma unroll
            for (int mt = 0; mt < 2; mt++)
                #pragma unroll
                for (int nt = 0; nt < 4; nt++) {
                    mma_tf32(acc[mt][nt], al[mt], bh[nt]);
                    mma_tf32(acc[mt][nt], ah[mt], bl[nt]);
                    mma_tf32(acc[mt][nt], ah[mt], bh[nt]);
                }
        }
        __syncthreads();
    }
    const float scale = 0.125f;
    #pragma unroll
    for (int mt = 0; mt < 2; mt++) {
        #pragma unroll
        for (int nt = 0; nt < 4; nt++) {
            int r0 = t0 + warpM * 32 + mt * 16 + (lane >> 2);
            int cb = s0 + warpN * 32 + nt * 8 + (lane & 3) * 2;
            #pragma unroll
            for (int half = 0; half < 2; half++) {
                int r = r0 + half * 8;
                float2 o = make_float2(acc[mt][nt][half * 2] * scale,
                                       acc[mt][nt][half * 2 + 1] * scale);
                *(float2*)(P + ((size_t)bh * Td + r) * Td + cb) = o;
            }
        }
    }
}

// ---------------- causal softmax per row (smem row buffer) -----------------
__global__ __launch_bounds__(256) void softmax_k(float* __restrict__ P) {
    __shared__ float buf[Td];
    const size_t r = blockIdx.x;
    const int t = (int)(r & (Td - 1));
    float* row = P + r * Td;
    const int n = t + 1;
    float m = -INFINITY;
    for (int i = threadIdx.x; i < n; i += 256) {
        float v = row[i];
        buf[i] = v;
        m = fmaxf(m, v);
    }
    m = block_reduce_max(m);
    float s = 0.0f;
    for (int i = threadIdx.x; i < n; i += 256) {
        float e = __expf(buf[i] - m);
        buf[i] = e;
        s += e;
    }
    s = block_reduce_sum(s);
    const float inv = 1.0f / s;
    for (int i = threadIdx.x; i < n; i += 256) row[i] = buf[i] * inv;
    const int fillEnd = ((t >> 6) << 6) + 64;
    for (int i = n + (int)threadIdx.x; i < fillEnd; i += 256) row[i] = 0.0f;
}

// ---------------- attn_mean: lower reads only, zeros written directly ------
__global__ __launch_bounds__(256) void attnmean_k(const float* __restrict__ P,
                                                  float* __restrict__ out) {
    const size_t i4 = (size_t)blockIdx.x * 256 + threadIdx.x;
    const int scol = (int)(i4 & (Td / 4 - 1)) * 4;
    const int t = (int)((i4 >> 9) & (Td - 1));
    const size_t off = (size_t)Hd * Td * Td;
    float4 o;
    if (scol > t) {
        o = make_float4(0.f, 0.f, 0.f, 0.f);
    } else {
        float4 a = *(const float4*)(P + i4 * 4);
        float4 b = *(const float4*)(P + i4 * 4 + off);
        o.x = 0.5f * (a.x + b.x); o.y = 0.5f * (a.y + b.y);
        o.z = 0.5f * (a.z + b.z); o.w = 0.5f * (a.w + b.w);
    }
    *(float4*)(out + i4 * 4) = o;
}

// ---------------- attn_out = P @ V (triangular), 3xTF32 --------------------
__global__ __launch_bounds__(128) void pv_tc(const float* __restrict__ P,
                                             const float* __restrict__ qkv,
                                             float* __restrict__ out) {
    const int bh = blockIdx.y;
    const int b = bh >> 4, h = bh & 15;
    const int t0 = blockIdx.x * 64;
    __shared__ float Ph[64][36], Pl[64][36];   // [m][k], 32-wide k slab
    __shared__ float Vh[32][72], Vl[32][72];   // [k][n]
    const int tid = threadIdx.x, lane = tid & 31, warp = tid >> 5;
    const int warpM = warp >> 1, warpN = warp & 1;
    float acc[2][4][4] = {};
    // NOTE: bound is t0+64 (not t0): the diagonal 64-block needs both 32-wide
    // slabs; P is zero-filled to the 64-boundary so the reads are safe.
    for (int s0 = 0; s0 < t0 + 64; s0 += 32) {
        #pragma unroll
        for (int i = 0; i < 4; i++) {
            int idx = tid + i * 128;
            {   // P tile: 64 x 32
                int r = idx >> 3, c = (idx & 7) * 4;
                float4 hi, lo;
                split4(*(const float4*)(P + ((size_t)bh * Td + t0 + r) * Td + s0 + c), hi, lo);
                *(float4*)&Ph[r][c] = hi; *(float4*)&Pl[r][c] = lo;
            }
            {   // V tile: 32 x 64
                int r = idx >> 4, c = (idx & 15) * 4;
                float4 hi, lo;
                split4(*(const float4*)(qkv + (size_t)(b * Td + s0 + r) * QKVs + 2 * Cd + h * 64 + c), hi, lo);
                *(float4*)&Vh[r][c] = hi; *(float4*)&Vl[r][c] = lo;
            }
        }
        __syncthreads();
        #pragma unroll
        for (int ks = 0; ks < 32; ks += 8) {
            uint32_t ah[2][4], al[2][4], bh[4][2], bl[4][2];
            #pragma unroll
            for (int mt = 0; mt < 2; mt++) {
                int r = warpM * 32 + mt * 16 + (lane >> 2);
                int c = ks + (lane & 3);
                ah[mt][0] = __float_as_uint(Ph[r][c]);
                ah[mt][1] = __float_as_uint(Ph[r + 8][c]);
                ah[mt][2] = __float_as_uint(Ph[r][c + 4]);
                ah[mt][3] = __float_as_uint(Ph[r + 8][c + 4]);
                al[mt][0] = __float_as_uint(Pl[r][c]);
                al[mt][1] = __float_as_uint(Pl[r + 8][c]);
                al[mt][2] = __float_as_uint(Pl[r][c + 4]);
                al[mt][3] = __float_as_uint(Pl[r + 8][c + 4]);
            }
            #pragma unroll
            for (int nt = 0; nt < 4; nt++) {
                int n = warpN * 32 + nt * 8 + (lane >> 2);
                int kk = ks + (lane & 3);
                bh[nt][0] = __float_as_uint(Vh[kk][n]);
                bh[nt][1] = __float_as_uint(Vh[kk + 4][n]);
                bl[nt][0] = __float_as_uint(Vl[kk][n]);
                bl[nt][1] = __float_as_uint(Vl[kk + 4][n]);
            }
            #pragma unroll
            for (int mt = 0; mt < 2; mt++)
                #pragma unroll
                for (int nt = 0; nt < 4; nt++) {
                    mma_tf32(acc[mt][nt], al[mt], bh[nt]);
                    mma_tf32(acc[mt][nt], ah[mt], bl[nt]);
                    mma_tf32(acc[mt][nt], ah[mt], bh[nt]);
                }
        }
        __syncthreads();
    }
    #pragma unroll
    for (int mt = 0; mt < 2; mt++) {
        #pragma unroll
        for (int nt = 0; nt < 4; nt++) {
            int r0 = t0 + warpM * 32 + mt * 16 + (lane >> 2);
            int cb = warpN * 32 + nt * 8 + (lane & 3) * 2;
            #pragma unroll
            for (int half = 0; half < 2; half++) {
                int r = r0 + half * 8;
                float2 o = make_float2(acc[mt][nt][half * 2], acc[mt][nt][half * 2 + 1]);
                *(float2*)(out + (size_t)(b * Td + r) * Cd + h * 64 + cb) = o;
            }
        }
    }
}

// ---------------- launch ---------------------------------------------------
extern "C" void kernel_launch(void* const* d_in, const int* in_sizes, int n_in,
                              void* d_out, int out_size) {
    const float* x      = (const float*)d_in[0];
    const float* ln1_w  = (const float*)d_in[1];
    const float* ln1_b  = (const float*)d_in[2];
    const float* w_qkv  = (const float*)d_in[3];
    const float* b_qkv  = (const float*)d_in[4];
    const float* w_proj = (const float*)d_in[5];
    const float* b_proj = (const float*)d_in[6];
    const float* ln2_w  = (const float*)d_in[7];
    const float* ln2_b  = (const float*)d_in[8];
    const float* w_fc   = (const float*)d_in[9];
    const float* b_fc   = (const float*)d_in[10];
    const float* w_fc2  = (const float*)d_in[11];
    const float* b_fc2  = (const float*)d_in[12];

    float* out_x    = (float*)d_out;
    float* out_attn = (float*)d_out + (size_t)Rows * Cd;

    float *gh, *gqkv, *gP, *gattn, *gx1, *gfc;
    cudaGetSymbolAddress((void**)&gh,   g_h);
    cudaGetSymbolAddress((void**)&gqkv, g_qkv);
    cudaGetSymbolAddress((void**)&gP,   g_P);
    cudaGetSymbolAddress((void**)&gattn,g_attn);
    cudaGetSymbolAddress((void**)&gx1,  g_x1);
    cudaGetSymbolAddress((void**)&gfc,  g_fc);

    ln_k<<<Rows, 256>>>(x, ln1_w, ln1_b, gh);
    tgemm_k<0><<<dim3(QKVs / 128, Rows / 128), 256>>>(Rows, QKVs, Cd, gh, w_qkv, b_qkv, nullptr, gqkv);
    scores_tc<<<dim3(Td / 64, Td / 64, Bd * Hd), 128>>>(gqkv, gP);
    softmax_k<<<Bd * Hd * Td, 256>>>(gP);
    attnmean_k<<<(unsigned)((size_t)Hd * Td * Td / 4 / 256), 256>>>(gP, out_attn);
    pv_tc<<<dim3(Td / 64, Bd * Hd), 128>>>(gP, gqkv, gattn);
    tgemm_k<1><<<dim3(Cd / 128, Rows / 128), 256>>>(Rows, Cd, Cd, gattn, w_proj, b_proj, x, gx1);
    ln_k<<<Rows, 256>>>(gx1, ln2_w, ln2_b, gh);
    tgemm_k<2><<<dim3(4 * Cd / 128, Rows / 128), 256>>>(Rows, 4 * Cd, Cd, gh, w_fc, b_fc, nullptr, gfc);
    tgemm_k<1><<<dim3(Cd / 128, Rows / 128), 256>>>(Rows, Cd, 4 * Cd, gfc, w_fc2, b_fc2, gx1, out_x);
}

// round 6
// speedup vs baseline: 2.2968x; 1.6968x over previous
#include <cuda_runtime.h>
#include <cuda_bf16.h>
#include <math.h>
#include <stdint.h>

// Problem constants
constexpr int Bd = 2;
constexpr int Td = 2048;
constexpr int Cd = 1024;
constexpr int Hd = 16;
constexpr int Rows = Bd * Td;   // 4096
constexpr int QKVs = 3 * Cd;    // 3072

// ---------------- scratch (device globals) ---------------------------------
__device__ float g_h   [Rows * Cd];
__device__ float g_qkv [Rows * QKVs];
__device__ float g_P   [(size_t)Bd * Hd * Td * Td];
__device__ float g_attn[Rows * Cd];
__device__ float g_x1  [Rows * Cd];
__device__ float g_fc  [Rows * 4 * Cd];

// ---------------- bf16 mma m16n8k16 + split helpers ------------------------
__device__ __forceinline__ void mma_bf16(float* c, const uint32_t* a, const uint32_t* b) {
    asm volatile(
        "mma.sync.aligned.m16n8k16.row.col.f32.bf16.bf16.f32 "
        "{%0,%1,%2,%3}, {%4,%5,%6,%7}, {%8,%9}, {%0,%1,%2,%3};\n"
        : "+f"(c[0]), "+f"(c[1]), "+f"(c[2]), "+f"(c[3])
        : "r"(a[0]), "r"(a[1]), "r"(a[2]), "r"(a[3]), "r"(b[0]), "r"(b[1]));
}

// pack two floats as bf16x2: 'even' -> low 16 bits (even k), 'odd' -> high
__device__ __forceinline__ uint32_t packb(float even, float odd) {
    uint32_t r;
    asm("cvt.rn.bf16x2.f32 %0, %1, %2;" : "=r"(r) : "f"(odd), "f"(even));
    return r;
}
// hi = bf16(x) (as float), lo = x - hi (exact fp32 residual)
__device__ __forceinline__ void splitb(float x, float& hi, float& lo) {
    float h = __bfloat162float(__float2bfloat16_rn(x));
    hi = h; lo = x - h;
}
__device__ __forceinline__ void splitb4(float4 v, float4& hi, float4& lo) {
    splitb(v.x, hi.x, lo.x); splitb(v.y, hi.y, lo.y);
    splitb(v.z, hi.z, lo.z); splitb(v.w, hi.w, lo.w);
}

// ---------------- block reductions -----------------------------------------
__device__ __forceinline__ float block_reduce_sum(float v) {
    __shared__ float sm[32];
    int lane = threadIdx.x & 31, wid = threadIdx.x >> 5;
    #pragma unroll
    for (int o = 16; o; o >>= 1) v += __shfl_down_sync(0xffffffffu, v, o);
    if (lane == 0) sm[wid] = v;
    __syncthreads();
    float r;
    if (wid == 0) {
        float t = (lane < 8) ? sm[lane] : 0.0f;
        #pragma unroll
        for (int o = 4; o; o >>= 1) t += __shfl_down_sync(0xffu, t, o);
        if (lane == 0) sm[0] = t;
    }
    __syncthreads();
    r = sm[0];
    __syncthreads();
    return r;
}

__device__ __forceinline__ float block_reduce_max(float v) {
    __shared__ float sm[32];
    int lane = threadIdx.x & 31, wid = threadIdx.x >> 5;
    #pragma unroll
    for (int o = 16; o; o >>= 1) v = fmaxf(v, __shfl_down_sync(0xffffffffu, v, o));
    if (lane == 0) sm[wid] = v;
    __syncthreads();
    float r;
    if (wid == 0) {
        float t = (lane < 8) ? sm[lane] : -INFINITY;
        #pragma unroll
        for (int o = 4; o; o >>= 1) t = fmaxf(t, __shfl_down_sync(0xffu, t, o));
        if (lane == 0) sm[0] = t;
    }
    __syncthreads();
    r = sm[0];
    __syncthreads();
    return r;
}

// ---------------- LayerNorm ------------------------------------------------
__global__ __launch_bounds__(256) void ln_k(const float* __restrict__ x,
                                            const float* __restrict__ w,
                                            const float* __restrict__ b,
                                            float* __restrict__ y) {
    const int row = blockIdx.x;
    const float* xr = x + (size_t)row * Cd;
    float4 v = *(const float4*)(xr + threadIdx.x * 4);
    float s  = v.x + v.y + v.z + v.w;
    float sq = v.x * v.x + v.y * v.y + v.z * v.z + v.w * v.w;
    float sum  = block_reduce_sum(s);
    float sumq = block_reduce_sum(sq);
    float mean = sum * (1.0f / Cd);
    float var  = sumq * (1.0f / Cd) - mean * mean;
    float rstd = rsqrtf(var + 1e-5f);
    int c = threadIdx.x * 4;
    float4 wv = *(const float4*)(w + c);
    float4 bv = *(const float4*)(b + c);
    float4 o;
    o.x = (v.x - mean) * rstd * wv.x + bv.x;
    o.y = (v.y - mean) * rstd * wv.y + bv.y;
    o.z = (v.z - mean) * rstd * wv.z + bv.z;
    o.w = (v.w - mean) * rstd * wv.w + bv.w;
    *(float4*)(y + (size_t)row * Cd + c) = o;
}

// ---------------- 3xBF16 GEMM (m16n8k16), hi/lo smem, reg prefetch ---------
// C[M,N] = A[M,K] @ B[K,N] + bias; EPI: 0 bias, 1 bias+res, 2 gelu(bias+.)
template <int EPI>
__global__ __launch_bounds__(256) void tgemm_k(int M, int N, int K,
                                               const float* __restrict__ A,
                                               const float* __restrict__ B,
                                               const float* __restrict__ bias,
                                               const float* __restrict__ res,
                                               float* __restrict__ C) {
    constexpr int BM = 128, BN = 128, BK = 16;
    __shared__ uint32_t Ah[BM][12], Al[BM][12];     // 8 data u32 + 4 pad (stride 12)
    __shared__ uint32_t Bh[8][136], Bl[8][136];     // kk rows, 128 n + 8 pad
    const int tid = threadIdx.x, lane = tid & 31, warp = tid >> 5;
    const int warpM = warp >> 2, warpN = warp & 3;  // 2 x 4 warps
    const size_t bM = (size_t)blockIdx.y * BM, bN = (size_t)blockIdx.x * BN;

    const int aRow = tid >> 2, aC = (tid & 3) * 4;  // A: rows aRow,+64; k cols aC..aC+3
    const int bK = warp * 2;                        // B: k rows bK, bK+1
    const int bCol = lane * 4;                      // n cols

    float4 ra[2], rba, rbb;
    #pragma unroll
    for (int i = 0; i < 2; i++)
        ra[i] = *(const float4*)(A + (bM + aRow + 64 * i) * K + aC);
    rba = *(const float4*)(B + (size_t)bK * N + bN + bCol);
    rbb = *(const float4*)(B + (size_t)(bK + 1) * N + bN + bCol);

    float acc[4][4][4] = {};
    for (int k0 = 0; k0 < K; k0 += BK) {
        // split current regs into hi/lo packed smem tiles
        #pragma unroll
        for (int i = 0; i < 2; i++) {
            float4 hi, lo;
            splitb4(ra[i], hi, lo);
            *(uint2*)&Ah[aRow + 64 * i][(tid & 3) * 2] =
                make_uint2(packb(hi.x, hi.y), packb(hi.z, hi.w));
            *(uint2*)&Al[aRow + 64 * i][(tid & 3) * 2] =
                make_uint2(packb(lo.x, lo.y), packb(lo.z, lo.w));
        }
        {
            float4 ha, la, hb, lb;
            splitb4(rba, ha, la);
            splitb4(rbb, hb, lb);
            *(uint4*)&Bh[warp][bCol] = make_uint4(packb(ha.x, hb.x), packb(ha.y, hb.y),
                                                  packb(ha.z, hb.z), packb(ha.w, hb.w));
            *(uint4*)&Bl[warp][bCol] = make_uint4(packb(la.x, lb.x), packb(la.y, lb.y),
                                                  packb(la.z, lb.z), packb(la.w, lb.w));
        }
        __syncthreads();
        if (k0 + BK < K) {
            #pragma unroll
            for (int i = 0; i < 2; i++)
                ra[i] = *(const float4*)(A + (bM + aRow + 64 * i) * K + k0 + BK + aC);
            rba = *(const float4*)(B + (size_t)(k0 + BK + bK) * N + bN + bCol);
            rbb = *(const float4*)(B + (size_t)(k0 + BK + bK + 1) * N + bN + bCol);
        }
        // single k16 step covers BK
        uint32_t a_h[4][4], a_l[4][4], b_h[4][2], b_l[4][2];
        const int kk = lane & 3, fr = lane >> 2;
        #pragma unroll
        for (int mt = 0; mt < 4; mt++) {
            int r = warpM * 64 + mt * 16 + fr;
            a_h[mt][0] = Ah[r][kk];     a_h[mt][1] = Ah[r + 8][kk];
            a_h[mt][2] = Ah[r][kk + 4]; a_h[mt][3] = Ah[r + 8][kk + 4];
            a_l[mt][0] = Al[r][kk];     a_l[mt][1] = Al[r + 8][kk];
            a_l[mt][2] = Al[r][kk + 4]; a_l[mt][3] = Al[r + 8][kk + 4];
        }
        #pragma unroll
        for (int nt = 0; nt < 4; nt++) {
            int n = warpN * 32 + nt * 8 + fr;
            b_h[nt][0] = Bh[kk][n]; b_h[nt][1] = Bh[kk + 4][n];
            b_l[nt][0] = Bl[kk][n]; b_l[nt][1] = Bl[kk + 4][n];
        }
        #pragma unroll
        for (int mt = 0; mt < 4; mt++)
            #pragma unroll
            for (int nt = 0; nt < 4; nt++) {
                mma_bf16(acc[mt][nt], a_l[mt], b_h[nt]);
                mma_bf16(acc[mt][nt], a_h[mt], b_l[nt]);
                mma_bf16(acc[mt][nt], a_h[mt], b_h[nt]);
            }
        __syncthreads();
    }
    // epilogue
    #pragma unroll
    for (int mt = 0; mt < 4; mt++) {
        #pragma unroll
        for (int nt = 0; nt < 4; nt++) {
            size_t r0 = bM + warpM * 64 + mt * 16 + (lane >> 2);
            size_t cb = bN + warpN * 32 + nt * 8 + (lane & 3) * 2;
            float b0 = bias[cb], b1 = bias[cb + 1];
            #pragma unroll
            for (int half = 0; half < 2; half++) {
                size_t r = r0 + half * 8;
                float v0 = acc[mt][nt][half * 2 + 0] + b0;
                float v1 = acc[mt][nt][half * 2 + 1] + b1;
                if (EPI == 1) {
                    const float* rp = res + r * N + cb;
                    v0 += rp[0]; v1 += rp[1];
                }
                if (EPI == 2) {
                    v0 = 0.5f * v0 * (1.0f + erff(v0 * 0.70710678118654752f));
                    v1 = 0.5f * v1 * (1.0f + erff(v1 * 0.70710678118654752f));
                }
                *(float2*)(C + r * N + cb) = make_float2(v0, v1);
            }
        }
    }
}

// ---------------- scores: S = Q K^T * scale (lower blocks), 3xBF16 ---------
__global__ __launch_bounds__(128) void scores_tc(const float* __restrict__ qkv,
                                                 float* __restrict__ P) {
    const int bh = blockIdx.z;
    const int b = bh >> 4, h = bh & 15;
    const int t0 = blockIdx.y * 64, s0 = blockIdx.x * 64;
    if (s0 > t0) return;
    __shared__ uint32_t Qh[64][36], Ql[64][36];   // [m][kk], 32 data + 4 pad
    __shared__ uint32_t Kh[64][36], Kl[64][36];   // [n][kk]
    const int tid = threadIdx.x, lane = tid & 31, warp = tid >> 5;
    const int warpM = warp >> 1, warpN = warp & 1;  // 2x2 warps, 32x32 each
    const float* qb = qkv + (size_t)(b * Td + t0) * QKVs + h * 64;
    const float* kb = qkv + (size_t)(b * Td + s0) * QKVs + Cd + h * 64;
    #pragma unroll
    for (int i = 0; i < 8; i++) {
        int idx = tid + i * 128;
        int r = idx >> 4, c4 = (idx & 15) * 4;
        float4 hi, lo;
        splitb4(*(const float4*)(qb + (size_t)r * QKVs + c4), hi, lo);
        *(uint2*)&Qh[r][c4 >> 1] = make_uint2(packb(hi.x, hi.y), packb(hi.z, hi.w));
        *(uint2*)&Ql[r][c4 >> 1] = make_uint2(packb(lo.x, lo.y), packb(lo.z, lo.w));
        splitb4(*(const float4*)(kb + (size_t)r * QKVs + c4), hi, lo);
        *(uint2*)&Kh[r][c4 >> 1] = make_uint2(packb(hi.x, hi.y), packb(hi.z, hi.w));
        *(uint2*)&Kl[r][c4 >> 1] = make_uint2(packb(lo.x, lo.y), packb(lo.z, lo.w));
    }
    __syncthreads();
    float acc[2][4][4] = {};
    #pragma unroll
    for (int ks = 0; ks < 4; ks++) {               // 4 x k16 steps
        const int kb0 = ks * 8 + (lane & 3), fr = lane >> 2;
        uint32_t a_h[2][4], a_l[2][4], b_h[4][2], b_l[4][2];
        #pragma unroll
        for (int mt = 0; mt < 2; mt++) {
            int r = warpM * 32 + mt * 16 + fr;
            a_h[mt][0] = Qh[r][kb0];     a_h[mt][1] = Qh[r + 8][kb0];
            a_h[mt][2] = Qh[r][kb0 + 4]; a_h[mt][3] = Qh[r + 8][kb0 + 4];
            a_l[mt][0] = Ql[r][kb0];     a_l[mt][1] = Ql[r + 8][kb0];
            a_l[mt][2] = Ql[r][kb0 + 4]; a_l[mt][3] = Ql[r + 8][kb0 + 4];
        }
        #pragma unroll
        for (int nt = 0; nt < 4; nt++) {
            int n = warpN * 32 + nt * 8 + fr;
            b_h[nt][0] = Kh[n][kb0]; b_h[nt][1] = Kh[n][kb0 + 4];
            b_l[nt][0] = Kl[n][kb0]; b_l[nt][1] = Kl[n][kb0 + 4];
        }
        #pragma unroll
        for (int mt = 0; mt < 2; mt++)
            #pragma unroll
            for (int nt = 0; nt < 4; nt++) {
                mma_bf16(acc[mt][nt], a_l[mt], b_h[nt]);
                mma_bf16(acc[mt][nt], a_h[mt], b_l[nt]);
                mma_bf16(acc[mt][nt], a_h[mt], b_h[nt]);
            }
    }
    const float scale = 0.125f;
    #pragma unroll
    for (int mt = 0; mt < 2; mt++) {
        #pragma unroll
        for (int nt = 0; nt < 4; nt++) {
            int r0 = t0 + warpM * 32 + mt * 16 + (lane >> 2);
            int cb = s0 + warpN * 32 + nt * 8 + (lane & 3) * 2;
            #pragma unroll
            for (int half = 0; half < 2; half++) {
                int r = r0 + half * 8;
                float2 o = make_float2(acc[mt][nt][half * 2] * scale,
                                       acc[mt][nt][half * 2 + 1] * scale);
                *(float2*)(P + ((size_t)bh * Td + r) * Td + cb) = o;
            }
        }
    }
}

// ---------------- causal softmax per row (smem row buffer) -----------------
__global__ __launch_bounds__(256) void softmax_k(float* __restrict__ P) {
    __shared__ float buf[Td];
    const size_t r = blockIdx.x;
    const int t = (int)(r & (Td - 1));
    float* row = P + r * Td;
    const int n = t + 1;
    float m = -INFINITY;
    for (int i = threadIdx.x; i < n; i += 256) {
        float v = row[i];
        buf[i] = v;
        m = fmaxf(m, v);
    }
    m = block_reduce_max(m);
    float s = 0.0f;
    for (int i = threadIdx.x; i < n; i += 256) {
        float e = __expf(buf[i] - m);
        buf[i] = e;
        s += e;
    }
    s = block_reduce_sum(s);
    const float inv = 1.0f / s;
    for (int i = threadIdx.x; i < n; i += 256) row[i] = buf[i] * inv;
    const int fillEnd = ((t >> 6) << 6) + 64;
    for (int i = n + (int)threadIdx.x; i < fillEnd; i += 256) row[i] = 0.0f;
}

// ---------------- attn_mean: lower reads only, zeros written directly ------
__global__ __launch_bounds__(256) void attnmean_k(const float* __restrict__ P,
                                                  float* __restrict__ out) {
    const size_t i4 = (size_t)blockIdx.x * 256 + threadIdx.x;
    const int scol = (int)(i4 & (Td / 4 - 1)) * 4;
    const int t = (int)((i4 >> 9) & (Td - 1));
    const size_t off = (size_t)Hd * Td * Td;
    float4 o;
    if (scol > t) {
        o = make_float4(0.f, 0.f, 0.f, 0.f);
    } else {
        float4 a = *(const float4*)(P + i4 * 4);
        float4 b = *(const float4*)(P + i4 * 4 + off);
        o.x = 0.5f * (a.x + b.x); o.y = 0.5f * (a.y + b.y);
        o.z = 0.5f * (a.z + b.z); o.w = 0.5f * (a.w + b.w);
    }
    *(float4*)(out + i4 * 4) = o;
}

// ---------------- attn_out = P @ V (triangular), 3xBF16 --------------------
__global__ __launch_bounds__(128) void pv_tc(const float* __restrict__ P,
                                             const float* __restrict__ qkv,
                                             float* __restrict__ out) {
    const int bh = blockIdx.y;
    const int b = bh >> 4, h = bh & 15;
    const int t0 = blockIdx.x * 64;
    __shared__ uint32_t Ph[64][36], Pl[64][36];   // [m][kk], 64-k slab packed
    __shared__ uint32_t Vh[32][72], Vl[32][72];   // [kk][n]
    const int tid = threadIdx.x, lane = tid & 31, warp = tid >> 5;
    const int warpM = warp >> 1, warpN = warp & 1;
    float acc[2][4][4] = {};
    for (int s0 = 0; s0 <= t0; s0 += 64) {        // diagonal block zero-filled
        #pragma unroll
        for (int i = 0; i < 8; i++) {             // P: 64 x 64 = 64 rows x 16 f4
            int idx = tid + i * 128;
            int r = idx >> 4, c4 = (idx & 15) * 4;
            float4 hi, lo;
            splitb4(*(const float4*)(P + ((size_t)bh * Td + t0 + r) * Td + s0 + c4), hi, lo);
            *(uint2*)&Ph[r][c4 >> 1] = make_uint2(packb(hi.x, hi.y), packb(hi.z, hi.w));
            *(uint2*)&Pl[r][c4 >> 1] = make_uint2(packb(lo.x, lo.y), packb(lo.z, lo.w));
        }
        #pragma unroll
        for (int i = 0; i < 4; i++) {             // V: 64k x 64n -> 32 kk x 16 f4
            int idx = tid + i * 128;
            int kkr = idx >> 4, n4 = (idx & 15) * 4;
            const float* vb = qkv + (size_t)(b * Td + s0) * QKVs + 2 * Cd + h * 64;
            float4 hA, lA, hB, lB;
            splitb4(*(const float4*)(vb + (size_t)(2 * kkr) * QKVs + n4), hA, lA);
            splitb4(*(const float4*)(vb + (size_t)(2 * kkr + 1) * QKVs + n4), hB, lB);
            *(uint4*)&Vh[kkr][n4] = make_uint4(packb(hA.x, hB.x), packb(hA.y, hB.y),
                                               packb(hA.z, hB.z), packb(hA.w, hB.w));
            *(uint4*)&Vl[kkr][n4] = make_uint4(packb(lA.x, lB.x), packb(lA.y, lB.y),
                                               packb(lA.z, lB.z), packb(lA.w, lB.w));
        }
        __syncthreads();
        #pragma unroll
        for (int ks = 0; ks < 4; ks++) {
            const int kb0 = ks * 8 + (lane & 3), fr = lane >> 2;
            uint32_t a_h[2][4], a_l[2][4], b_h[4][2], b_l[4][2];
            #pragma unroll
            for (int mt = 0; mt < 2; mt++) {
                int r = warpM * 32 + mt * 16 + fr;
                a_h[mt][0] = Ph[r][kb0];     a_h[mt][1] = Ph[r + 8][kb0];
                a_h[mt][2] = Ph[r][kb0 + 4]; a_h[mt][3] = Ph[r + 8][kb0 + 4];
                a_l[mt][0] = Pl[r][kb0];     a_l[mt][1] = Pl[r + 8][kb0];
                a_l[mt][2] = Pl[r][kb0 + 4]; a_l[mt][3] = Pl[r + 8][kb0 + 4];
            }
            #pragma unroll
            for (int nt = 0; nt < 4; nt++) {
                int n = warpN * 32 + nt * 8 + fr;
                b_h[nt][0] = Vh[kb0][n]; b_h[nt][1] = Vh[kb0 + 4][n];
                b_l[nt][0] = Vl[kb0][n]; b_l[nt][1] = Vl[kb0 + 4][n];
            }
            #pragma unroll
            for (int mt = 0; mt < 2; mt++)
                #pragma unroll
                for (int nt = 0; nt < 4; nt++) {
                    mma_bf16(acc[mt][nt], a_l[mt], b_h[nt]);
                    mma_bf16(acc[mt][nt], a_h[mt], b_l[nt]);
                    mma_bf16(acc[mt][nt], a_h[mt], b_h[nt]);
                }
        }
        __syncthreads();
    }
    #pragma unroll
    for (int mt = 0; mt < 2; mt++) {
        #pragma unroll
        for (int nt = 0; nt < 4; nt++) {
            int r0 = t0 + warpM * 32 + mt * 16 + (lane >> 2);
            int cb = warpN * 32 + nt * 8 + (lane & 3) * 2;
            #pragma unroll
            for (int half = 0; half < 2; half++) {
                int r = r0 + half * 8;
                float2 o = make_float2(acc[mt][nt][half * 2], acc[mt][nt][half * 2 + 1]);
                *(float2*)(out + (size_t)(b * Td + r) * Cd + h * 64 + cb) = o;
            }
        }
    }
}

// ---------------- launch ---------------------------------------------------
extern "C" void kernel_launch(void* const* d_in, const int* in_sizes, int n_in,
                              void* d_out, int out_size) {
    const float* x      = (const float*)d_in[0];
    const float* ln1_w  = (const float*)d_in[1];
    const float* ln1_b  = (const float*)d_in[2];
    const float* w_qkv  = (const float*)d_in[3];
    const float* b_qkv  = (const float*)d_in[4];
    const float* w_proj = (const float*)d_in[5];
    const float* b_proj = (const float*)d_in[6];
    const float* ln2_w  = (const float*)d_in[7];
    const float* ln2_b  = (const float*)d_in[8];
    const float* w_fc   = (const float*)d_in[9];
    const float* b_fc   = (const float*)d_in[10];
    const float* w_fc2  = (const float*)d_in[11];
    const float* b_fc2  = (const float*)d_in[12];

    float* out_x    = (float*)d_out;
    float* out_attn = (float*)d_out + (size_t)Rows * Cd;

    float *gh, *gqkv, *gP, *gattn, *gx1, *gfc;
    cudaGetSymbolAddress((void**)&gh,   g_h);
    cudaGetSymbolAddress((void**)&gqkv, g_qkv);
    cudaGetSymbolAddress((void**)&gP,   g_P);
    cudaGetSymbolAddress((void**)&gattn,g_attn);
    cudaGetSymbolAddress((void**)&gx1,  g_x1);
    cudaGetSymbolAddress((void**)&gfc,  g_fc);

    ln_k<<<Rows, 256>>>(x, ln1_w, ln1_b, gh);
    tgemm_k<0><<<dim3(QKVs / 128, Rows / 128), 256>>>(Rows, QKVs, Cd, gh, w_qkv, b_qkv, nullptr, gqkv);
    scores_tc<<<dim3(Td / 64, Td / 64, Bd * Hd), 128>>>(gqkv, gP);
    softmax_k<<<Bd * Hd * Td, 256>>>(gP);
    attnmean_k<<<(unsigned)((size_t)Hd * Td * Td / 4 / 256), 256>>>(gP, out_attn);
    pv_tc<<<dim3(Td / 64, Bd * Hd), 128>>>(gP, gqkv, gattn);
    tgemm_k<1><<<dim3(Cd / 128, Rows / 128), 256>>>(Rows, Cd, Cd, gattn, w_proj, b_proj, x, gx1);
    ln_k<<<Rows, 256>>>(gx1, ln2_w, ln2_b, gh);
    tgemm_k<2><<<dim3(4 * Cd / 128, Rows / 128), 256>>>(Rows, 4 * Cd, Cd, gh, w_fc, b_fc, nullptr, gfc);
    tgemm_k<1><<<dim3(Cd / 128, Rows / 128), 256>>>(Rows, Cd, 4 * Cd, gfc, w_fc2, b_fc2, gx1, out_x);
}